// round 1
// baseline (speedup 1.0000x reference)
#include <cuda_runtime.h>

#define HID   51
#define GATES 204          // 4*HID
#define SEQ   999
#define BATCH 4096
#define BT    14           // batch rows per block
#define NBLK  ((BATCH + BT - 1) / BT)   // 293
#define CHUNK 111          // 999 = 9*111
#define HPAD  52           // h row stride (13 float4)
#define GPAD  (BT + 1)     // 15, coprime with 32 -> conflict-free

__device__ __forceinline__ float sigf(float x) {
    // saturation-safe: x->-inf => 0, x->+inf => 1
    return __fdividef(1.0f, 1.0f + __expf(-x));
}
__device__ __forceinline__ float tanh_(float x) {
    // 2*sigmoid(2x)-1: saturation-safe at both ends
    return __fdividef(2.0f, 1.0f + __expf(-2.0f * x)) - 1.0f;
}

__global__ __launch_bounds__(256, 2)
void lstm_persistent(const float* __restrict__ input,
                     const float* __restrict__ W_ih,
                     const float* __restrict__ W_hh,
                     const float* __restrict__ b_ih,
                     const float* __restrict__ b_hh,
                     const float* __restrict__ W_fc,
                     const float* __restrict__ b_fc,
                     float* __restrict__ out)
{
    __shared__ float h_sh[BT * HPAD];            // h_{t-1}, padded rows (pad stays 0)
    __shared__ float gates_sh[GATES * GPAD];     // [row][b]
    __shared__ float x_sh[BT * CHUNK];           // input chunk

    const int tid = threadIdx.x;
    const int b0  = blockIdx.x * BT;
    const int B_local = min(BT, BATCH - b0);     // 14 everywhere, 8 on last block

    // ---- per-thread row weights in registers ----
    float whh[HPAD];
    float bias = 0.0f, wih = 0.0f;
    if (tid < GATES) {
        bias = b_ih[tid] + b_hh[tid];
        wih  = W_ih[tid];                        // INPUT==1 -> scalar per gate row
        #pragma unroll
        for (int k = 0; k < HID; k++) whh[k] = W_hh[tid * HID + k];
    } else if (tid == GATES) {                   // fused FC row
        bias = b_fc[0];
        #pragma unroll
        for (int k = 0; k < HID; k++) whh[k] = W_fc[k];
    } else {
        #pragma unroll
        for (int k = 0; k < HID; k++) whh[k] = 0.0f;
    }
    whh[HID] = 0.0f;                             // pad weight (k=51)

    // zero h (including pad column, which then never changes)
    for (int e = tid; e < BT * HPAD; e += 256) h_sh[e] = 0.0f;

    // ---- fixed elementwise mapping + c state in registers ----
    int eb[3], ek[3];
    float creg[3];
    #pragma unroll
    for (int r = 0; r < 3; r++) {
        int e = tid + 256 * r;
        eb[r] = e / HID;
        ek[r] = e - eb[r] * HID;
        creg[r] = 0.0f;
    }

    const bool is_gate = (tid < GATES);
    const bool is_fc   = (tid == GATES);

    for (int t = 0; t <= SEQ; ++t) {
        // stage next input chunk (disjoint from elementwise's h/gates traffic)
        if (t < SEQ && (t % CHUNK) == 0) {
            int n = B_local * CHUNK;
            for (int e = tid; e < n; e += 256) {
                int b  = e / CHUNK;
                int tc = e - b * CHUNK;
                x_sh[e] = input[(size_t)(b0 + b) * SEQ + (t + tc)];
            }
        }
        __syncthreads();   // A: h_{t-1}, x chunk ready

        // ---- GEMM phase: gates_t (rows 0..203) and y_{t-1} (row 204) ----
        bool act = is_gate ? (t < SEQ) : (is_fc && t > 0);
        if (act) {
            int tc = t % CHUNK;
            for (int b = 0; b < B_local; b += 2) {      // B_local is even (14 or 8)
                float a0 = fmaf(wih, x_sh[b * CHUNK + tc], bias);        // wih==0 for fc
                float a1 = fmaf(wih, x_sh[(b + 1) * CHUNK + tc], bias);
                const float4* h40 = reinterpret_cast<const float4*>(h_sh + b * HPAD);
                const float4* h41 = reinterpret_cast<const float4*>(h_sh + (b + 1) * HPAD);
                #pragma unroll
                for (int q = 0; q < 13; q++) {          // 52 = 13 x float4 (pad term is 0*0)
                    float4 u = h40[q];
                    float4 v = h41[q];
                    a0 = fmaf(u.x, whh[4 * q + 0], a0);
                    a1 = fmaf(v.x, whh[4 * q + 0], a1);
                    a0 = fmaf(u.y, whh[4 * q + 1], a0);
                    a1 = fmaf(v.y, whh[4 * q + 1], a1);
                    a0 = fmaf(u.z, whh[4 * q + 2], a0);
                    a1 = fmaf(v.z, whh[4 * q + 2], a1);
                    a0 = fmaf(u.w, whh[4 * q + 3], a0);
                    a1 = fmaf(v.w, whh[4 * q + 3], a1);
                }
                if (is_gate) {
                    gates_sh[tid * GPAD + b]     = a0;
                    gates_sh[tid * GPAD + b + 1] = a1;
                } else {
                    out[(size_t)(b0 + b)     * SEQ + (t - 1)] = a0;
                    out[(size_t)(b0 + b + 1) * SEQ + (t - 1)] = a1;
                }
            }
        }
        __syncthreads();   // B: gates ready; GEMM done reading h_{t-1}

        // ---- elementwise LSTM cell update -> h_t ----
        if (t < SEQ) {
            #pragma unroll
            for (int r = 0; r < 3; r++) {
                int e = tid + 256 * r;
                if (e < B_local * HID) {
                    int b = eb[r], k = ek[r];
                    float gi = gates_sh[(k          ) * GPAD + b];
                    float gf = gates_sh[(k +     HID) * GPAD + b];
                    float gg = gates_sh[(k + 2 * HID) * GPAD + b];
                    float go = gates_sh[(k + 3 * HID) * GPAD + b];
                    float c  = sigf(gf) * creg[r] + sigf(gi) * tanh_(gg);
                    creg[r]  = c;
                    h_sh[b * HPAD + k] = sigf(go) * tanh_(c);
                }
            }
        }
    }
}

extern "C" void kernel_launch(void* const* d_in, const int* in_sizes, int n_in,
                              void* d_out, int out_size) {
    const float* input = (const float*)d_in[0];
    const float* W_ih  = (const float*)d_in[1];
    const float* W_hh  = (const float*)d_in[2];
    const float* b_ih  = (const float*)d_in[3];
    const float* b_hh  = (const float*)d_in[4];
    const float* W_fc  = (const float*)d_in[5];
    const float* b_fc  = (const float*)d_in[6];
    // d_in[7] = future (static 0 in this problem)
    lstm_persistent<<<NBLK, 256>>>(input, W_ih, W_hh, b_ih, b_hh, W_fc, b_fc,
                                   (float*)d_out);
}